// round 11
// baseline (speedup 1.0000x reference)
#include <cuda_runtime.h>
#include <cstdint>

#define NN 50000
#define IND 1024
#define MIDD 256
#define EE_MAX 1600000

typedef unsigned long long ull;

// ---- scratch (no runtime allocation allowed) ----
__device__ __align__(128) float g_deg[NN];
__device__ __align__(128) float g_dis[NN];
__device__ __align__(128) float g_norm[EE_MAX];
__device__ __align__(128) int   g_src[EE_MAX];
__device__ __align__(128) int   g_dst[EE_MAX];
__device__ int g_is64;
__device__ __align__(128) float g_bufA[(size_t)NN * MIDD];   // xw, then h
__device__ __align__(128) float g_bufB[(size_t)NN * MIDD];   // agg1, then agg2

// ---- packed f32x2 helpers (Blackwell FFMA2 path) ----
__device__ __forceinline__ ull pack2(float x, float y) {
    ull r; asm("mov.b64 %0, {%1, %2};" : "=l"(r) : "f"(x), "f"(y)); return r;
}
__device__ __forceinline__ ull bcast2(float x) {
    ull r; asm("mov.b64 %0, {%1, %1};" : "=l"(r) : "f"(x)); return r;
}
__device__ __forceinline__ void fma2(ull& d, ull a, ull b) {
    asm("fma.rn.f32x2 %0, %1, %2, %0;" : "+l"(d) : "l"(a), "l"(b));
}
__device__ __forceinline__ float2 unpk(ull v) {
    float2 f; asm("mov.b64 {%0, %1}, %2;" : "=f"(f.x), "=f"(f.y) : "l"(v)); return f;
}

// ---- edge-index dtype detection + conversion ----
// If the indices are int64 (values < 50000), every odd int32 word is 0.
// If they are int32, the odd words are random node ids (~never all zero).
__global__ void k_detect(const int* __restrict__ ei32, int E) {
    __shared__ int nz;
    if (threadIdx.x == 0) nz = 0;
    __syncthreads();
    int samples = (E < 2048) ? E : 2048;
    for (int i = threadIdx.x; i < samples; i += blockDim.x) {
        if (ei32[2 * i + 1] != 0) atomicOr(&nz, 1);
    }
    __syncthreads();
    if (threadIdx.x == 0) g_is64 = (nz == 0) ? 1 : 0;
}

__global__ void k_convert(const void* __restrict__ ei, int E, int n) {
    int e = blockIdx.x * blockDim.x + threadIdx.x;
    if (e >= E) return;
    int s, d;
    if (g_is64) {
        const long long* p = (const long long*)ei;
        s = (int)p[e];
        d = (int)p[E + e];
    } else {
        const int* p = (const int*)ei;
        s = p[e];
        d = p[E + e];
    }
    // clamp defensively: a bad index becomes a rel_err, not a crash
    s = min(max(s, 0), n - 1);
    d = min(max(d, 0), n - 1);
    g_src[e] = s;
    g_dst[e] = d;
}

// ---- degree / normalization ----
__global__ void k_init_deg(int n) {
    int i = blockIdx.x * blockDim.x + threadIdx.x;
    if (i < n) g_deg[i] = 1.0f;                      // self-loop
}
__global__ void k_deg(int E) {
    int e = blockIdx.x * blockDim.x + threadIdx.x;
    if (e < E) atomicAdd(&g_deg[g_dst[e]], 1.0f);
}
__global__ void k_dis(int n) {
    int i = blockIdx.x * blockDim.x + threadIdx.x;
    if (i < n) g_dis[i] = rsqrtf(g_deg[i]);
}
__global__ void k_norm(int E) {
    int e = blockIdx.x * blockDim.x + threadIdx.x;
    if (e < E) g_norm[e] = g_dis[g_src[e]] * g_dis[g_dst[e]];
}

// ---- self-loop init: bufB = dis^2 * bufA ----
__global__ void k_selfinit(int n) {
    int idx = blockIdx.x * blockDim.x + threadIdx.x;
    int total = n * (MIDD / 4);
    if (idx >= total) return;
    int node = idx >> 6;
    float ds = g_dis[node];
    float w = ds * ds;
    float4 v = ((const float4*)g_bufA)[idx];
    v.x *= w; v.y *= w; v.z *= w; v.w *= w;
    ((float4*)g_bufB)[idx] = v;
}

// ---- fused: h = relu(agg1 + b1); bufA = h; bufB = dis^2 * h (in place) ----
__global__ void k_relu_bias(const float* __restrict__ b1, int n) {
    int idx = blockIdx.x * blockDim.x + threadIdx.x;
    int total = n * (MIDD / 4);
    if (idx >= total) return;
    int node = idx >> 6;
    int j = idx & 63;
    float4 b = ((const float4*)b1)[j];
    float4 v = ((const float4*)g_bufB)[idx];
    v.x = fmaxf(v.x + b.x, 0.f);
    v.y = fmaxf(v.y + b.y, 0.f);
    v.z = fmaxf(v.z + b.z, 0.f);
    v.w = fmaxf(v.w + b.w, 0.f);
    ((float4*)g_bufA)[idx] = v;
    float ds = g_dis[node];
    float w = ds * ds;
    v.x *= w; v.y *= w; v.z *= w; v.w *= w;
    ((float4*)g_bufB)[idx] = v;
}

// ---- edge aggregation: one warp per edge, float4 gather + scalar RED scatter ----
__global__ void k_edge_agg(const float* __restrict__ feat,
                           float* __restrict__ out, int E) {
    int lane = threadIdx.x & 31;
    int gw = (blockIdx.x * blockDim.x + threadIdx.x) >> 5;
    int nw = (gridDim.x * blockDim.x) >> 5;
    for (int e = gw; e < E; e += nw) {
        int s = __ldg(&g_src[e]);
        int d = __ldg(&g_dst[e]);
        float w = __ldg(&g_norm[e]);
        const float4* f = ((const float4*)feat) + (size_t)s * 64 + lane;
        float* ob = out + (size_t)d * 256 + lane * 4;
        float4 v0 = __ldg(f);
        float4 v1 = __ldg(f + 32);
        atomicAdd(ob + 0,   w * v0.x);
        atomicAdd(ob + 1,   w * v0.y);
        atomicAdd(ob + 2,   w * v0.z);
        atomicAdd(ob + 3,   w * v0.w);
        atomicAdd(ob + 128, w * v1.x);
        atomicAdd(ob + 129, w * v1.y);
        atomicAdd(ob + 130, w * v1.z);
        atomicAdd(ob + 131, w * v1.w);
    }
}

// ---- 128x128x16 SGEMM, 8x8 micro-tile, packed fma.rn.f32x2 accumulators ----
// C[M,N] = A[M,K] @ B[K,N] (+ bias[N] if non-null)
__global__ __launch_bounds__(256) void sgemm128(
    const float* __restrict__ A, const float* __restrict__ B,
    float* __restrict__ C, const float* __restrict__ bias,
    int M, int N, int K)
{
    __shared__ float As[16][132];   // transposed A tile, +4 pad
    __shared__ float Bs[16][128];
    const int tid = threadIdx.x;
    const int tx = tid & 15;
    const int ty = tid >> 4;
    const int rowBase = blockIdx.y * 128;
    const int colBase = blockIdx.x * 128;

    ull acc[4][8];
#pragma unroll
    for (int i = 0; i < 4; i++)
#pragma unroll
        for (int j = 0; j < 8; j++) acc[i][j] = 0ULL;

    for (int k0 = 0; k0 < K; k0 += 16) {
        // load A tile (transpose into As[k][m])
#pragma unroll
        for (int i = 0; i < 2; i++) {
            int idx = tid + i * 256;
            int r = idx >> 2, q = idx & 3;
            int gr = rowBase + r;
            float4 v = make_float4(0.f, 0.f, 0.f, 0.f);
            if (gr < M) v = *(const float4*)(A + (size_t)gr * K + (k0 + q * 4));
            As[q * 4 + 0][r] = v.x;
            As[q * 4 + 1][r] = v.y;
            As[q * 4 + 2][r] = v.z;
            As[q * 4 + 3][r] = v.w;
        }
        // load B tile
#pragma unroll
        for (int i = 0; i < 2; i++) {
            int idx = tid + i * 256;
            int kr = idx >> 5, nc = (idx & 31) << 2;
            *(float4*)&Bs[kr][nc] =
                *(const float4*)(B + (size_t)(k0 + kr) * N + (colBase + nc));
        }
        __syncthreads();
#pragma unroll
        for (int k = 0; k < 16; k++) {
            float4 a0 = *(const float4*)&As[k][ty * 4];
            float4 a1 = *(const float4*)&As[k][64 + ty * 4];
            float4 b0 = *(const float4*)&Bs[k][tx * 4];
            float4 b1 = *(const float4*)&Bs[k][64 + tx * 4];
            ull ap0 = pack2(a0.x, a0.y), ap1 = pack2(a0.z, a0.w);
            ull ap2 = pack2(a1.x, a1.y), ap3 = pack2(a1.z, a1.w);
            float bv[8] = {b0.x, b0.y, b0.z, b0.w, b1.x, b1.y, b1.z, b1.w};
#pragma unroll
            for (int j = 0; j < 8; j++) {
                ull bb = bcast2(bv[j]);
                fma2(acc[0][j], ap0, bb);
                fma2(acc[1][j], ap1, bb);
                fma2(acc[2][j], ap2, bb);
                fma2(acc[3][j], ap3, bb);
            }
        }
        __syncthreads();
    }

    float4 bb0 = make_float4(0.f, 0.f, 0.f, 0.f), bb1 = bb0;
    if (bias) {
        bb0 = *(const float4*)(bias + colBase + tx * 4);
        bb1 = *(const float4*)(bias + colBase + 64 + tx * 4);
    }
#pragma unroll
    for (int rp = 0; rp < 4; rp++) {
        float2 u[8];
#pragma unroll
        for (int j = 0; j < 8; j++) u[j] = unpk(acc[rp][j]);
        int rloc = (rp >> 1) * 64 + ty * 4 + (rp & 1) * 2;
#pragma unroll
        for (int h = 0; h < 2; h++) {
            int r = rowBase + rloc + h;
            if (r < M) {
                float4 c0, c1;
                c0.x = (h ? u[0].y : u[0].x) + bb0.x;
                c0.y = (h ? u[1].y : u[1].x) + bb0.y;
                c0.z = (h ? u[2].y : u[2].x) + bb0.z;
                c0.w = (h ? u[3].y : u[3].x) + bb0.w;
                c1.x = (h ? u[4].y : u[4].x) + bb1.x;
                c1.y = (h ? u[5].y : u[5].x) + bb1.y;
                c1.z = (h ? u[6].y : u[6].x) + bb1.z;
                c1.w = (h ? u[7].y : u[7].x) + bb1.w;
                *(float4*)(C + (size_t)r * N + colBase + tx * 4) = c0;
                *(float4*)(C + (size_t)r * N + colBase + 64 + tx * 4) = c1;
            }
        }
    }
}

extern "C" void kernel_launch(void* const* d_in, const int* in_sizes, int n_in,
                              void* d_out, int out_size) {
    if (n_in < 6) return;
    const float* x  = (const float*)d_in[0];
    const void*  ei = d_in[1];
    const float* W1 = (const float*)d_in[2];
    const float* b1 = (const float*)d_in[3];
    const float* W2 = (const float*)d_in[4];
    const float* b2 = (const float*)d_in[5];

    int n = in_sizes[0] / IND;     // 50000
    int E = in_sizes[1] / 2;       // 1600000

    float *bufA = nullptr, *bufB = nullptr;
    cudaGetSymbolAddress((void**)&bufA, g_bufA);
    cudaGetSymbolAddress((void**)&bufB, g_bufB);

    const int T = 256;
    int nb_n  = (n + T - 1) / T;
    int nb_e  = (E + T - 1) / T;
    int nb_f4 = (n * (MIDD / 4) + T - 1) / T;

    // edge-index dtype detection + int32 materialization
    k_detect<<<1, 256>>>((const int*)ei, E);
    k_convert<<<nb_e, T>>>(ei, E, n);

    // normalization coefficients
    k_init_deg<<<nb_n, T>>>(n);
    k_deg<<<nb_e, T>>>(E);
    k_dis<<<nb_n, T>>>(n);
    k_norm<<<nb_e, T>>>(E);

    // layer 1: xw = X @ W1  (bias applied after aggregation)
    sgemm128<<<dim3(MIDD / 128, (n + 127) / 128), 256>>>(x, W1, bufA, nullptr, n, MIDD, IND);
    // agg1 = D^-1/2 (A+I) D^-1/2 @ xw
    k_selfinit<<<nb_f4, T>>>(n);
    k_edge_agg<<<8192, 256>>>(bufA, bufB, E);
    // h = relu(agg1 + b1); seed agg2 with self-loop term
    k_relu_bias<<<nb_f4, T>>>(b1, n);
    // agg2 = D^-1/2 (A+I) D^-1/2 @ h   (aggregate BEFORE W2: A(hW2) == (Ah)W2)
    k_edge_agg<<<8192, 256>>>(bufA, bufB, E);
    // out = agg2 @ W2 + b2
    sgemm128<<<dim3(IND / 128, (n + 127) / 128), 256>>>(bufB, W2, (float*)d_out, b2, n, IND, MIDD);
}

// round 17
// speedup vs baseline: 1.1758x; 1.1758x over previous
#include <cuda_runtime.h>
#include <cuda_bf16.h>
#include <cstdint>

#define NN 50000
#define IND 1024
#define MIDD 256
#define EE_MAX 1600000

typedef unsigned long long ull;

// ---- scratch (no runtime allocation allowed) ----
__device__ __align__(128) float g_deg[NN];
__device__ __align__(128) float g_dis[NN];
__device__ __align__(128) float g_norm[EE_MAX];
__device__ __align__(128) int   g_src[EE_MAX];
__device__ __align__(128) int   g_dst[EE_MAX];
__device__ int g_is64;
__device__ __align__(128) float g_bufA[(size_t)NN * MIDD];   // xw, then h
__device__ __align__(128) float g_bufB[(size_t)NN * MIDD];   // agg1, then agg2
// transposed hi/lo bf16 weights: Wt[n][k] (K-major)
__device__ __align__(128) __nv_bfloat16 g_w1t_hi[(size_t)MIDD * IND];
__device__ __align__(128) __nv_bfloat16 g_w1t_lo[(size_t)MIDD * IND];
__device__ __align__(128) __nv_bfloat16 g_w2t_hi[(size_t)IND * MIDD];
__device__ __align__(128) __nv_bfloat16 g_w2t_lo[(size_t)IND * MIDD];
// hi/lo bf16 split of the current GEMM A operand
__device__ __align__(128) __nv_bfloat16 g_ah[(size_t)NN * IND];
__device__ __align__(128) __nv_bfloat16 g_al[(size_t)NN * IND];

// ================= small PTX helpers (all baseline sm_80+; no 'a' features) ==
__device__ __forceinline__ uint32_t smem_u32(const void* p) {
    uint32_t a;
    asm("{ .reg .u64 t; cvta.to.shared.u64 t, %1; cvt.u32.u64 %0, t; }"
        : "=r"(a) : "l"(p));
    return a;
}
__device__ __forceinline__ void ldsm_x4(uint32_t* r, uint32_t a) {
    asm volatile("ldmatrix.sync.aligned.m8n8.x4.shared.b16 {%0,%1,%2,%3}, [%4];"
                 : "=r"(r[0]), "=r"(r[1]), "=r"(r[2]), "=r"(r[3]) : "r"(a));
}
__device__ __forceinline__ void ldsm_x2(uint32_t* r, uint32_t a) {
    asm volatile("ldmatrix.sync.aligned.m8n8.x2.shared.b16 {%0,%1}, [%2];"
                 : "=r"(r[0]), "=r"(r[1]) : "r"(a));
}
__device__ __forceinline__ void mma_bf16(float* c, const uint32_t* a, const uint32_t* b) {
    asm volatile(
        "mma.sync.aligned.m16n8k16.row.col.f32.bf16.bf16.f32 "
        "{%0,%1,%2,%3}, {%4,%5,%6,%7}, {%8,%9}, {%0,%1,%2,%3};"
        : "+f"(c[0]), "+f"(c[1]), "+f"(c[2]), "+f"(c[3])
        : "r"(a[0]), "r"(a[1]), "r"(a[2]), "r"(a[3]), "r"(b[0]), "r"(b[1]));
}

// ================= edge-index dtype detection + conversion =================
__global__ void k_detect(const int* __restrict__ ei32, int E) {
    __shared__ int nz;
    if (threadIdx.x == 0) nz = 0;
    __syncthreads();
    int samples = (E < 2048) ? E : 2048;
    for (int i = threadIdx.x; i < samples; i += blockDim.x)
        if (ei32[2 * i + 1] != 0) atomicOr(&nz, 1);
    __syncthreads();
    if (threadIdx.x == 0) g_is64 = (nz == 0) ? 1 : 0;
}
__global__ void k_convert(const void* __restrict__ ei, int E, int n) {
    int e = blockIdx.x * blockDim.x + threadIdx.x;
    if (e >= E) return;
    int s, d;
    if (g_is64) {
        const long long* p = (const long long*)ei;
        s = (int)p[e]; d = (int)p[E + e];
    } else {
        const int* p = (const int*)ei;
        s = p[e]; d = p[E + e];
    }
    s = min(max(s, 0), n - 1);
    d = min(max(d, 0), n - 1);
    g_src[e] = s;
    g_dst[e] = d;
}

// ================= degree / normalization =================
__global__ void k_init_deg(int n) {
    int i = blockIdx.x * blockDim.x + threadIdx.x;
    if (i < n) g_deg[i] = 1.0f;
}
__global__ void k_deg(int E) {
    int e = blockIdx.x * blockDim.x + threadIdx.x;
    if (e < E) atomicAdd(&g_deg[g_dst[e]], 1.0f);
}
__global__ void k_dis(int n) {
    int i = blockIdx.x * blockDim.x + threadIdx.x;
    if (i < n) g_dis[i] = rsqrtf(g_deg[i]);
}
__global__ void k_norm(int E) {
    int e = blockIdx.x * blockDim.x + threadIdx.x;
    if (e < E) g_norm[e] = g_dis[g_src[e]] * g_dis[g_dst[e]];
}

// ================= weight transpose + hi/lo bf16 split =====================
// W [K,N] row-major -> Th/Tl [N,K]
__global__ void k_wt(const float* __restrict__ W, __nv_bfloat16* __restrict__ Th,
                     __nv_bfloat16* __restrict__ Tl, int K, int N) {
    int idx = blockIdx.x * blockDim.x + threadIdx.x;
    if (idx >= K * N) return;
    int nn = idx / K, kk = idx - nn * K;
    float w = W[(size_t)kk * N + nn];
    __nv_bfloat16 h = __float2bfloat16(w);
    __nv_bfloat16 l = __float2bfloat16(w - __bfloat162float(h));
    Th[idx] = h;
    Tl[idx] = l;
}

// ================= fp32 -> bf16 hi/lo split (A operand), float4-vectorized ==
__global__ void k_split(const float* __restrict__ A, __nv_bfloat16* __restrict__ H,
                        __nv_bfloat16* __restrict__ L, int total4) {
    int i = blockIdx.x * blockDim.x + threadIdx.x;
    if (i >= total4) return;
    float4 v = ((const float4*)A)[i];
    __nv_bfloat16 h0 = __float2bfloat16(v.x);
    __nv_bfloat16 h1 = __float2bfloat16(v.y);
    __nv_bfloat16 h2 = __float2bfloat16(v.z);
    __nv_bfloat16 h3 = __float2bfloat16(v.w);
    __nv_bfloat16 l0 = __float2bfloat16(v.x - __bfloat162float(h0));
    __nv_bfloat16 l1 = __float2bfloat16(v.y - __bfloat162float(h1));
    __nv_bfloat16 l2 = __float2bfloat16(v.z - __bfloat162float(h2));
    __nv_bfloat16 l3 = __float2bfloat16(v.w - __bfloat162float(h3));
    ull ph = (ull)__bfloat16_as_ushort(h0) | ((ull)__bfloat16_as_ushort(h1) << 16) |
             ((ull)__bfloat16_as_ushort(h2) << 32) | ((ull)__bfloat16_as_ushort(h3) << 48);
    ull pl = (ull)__bfloat16_as_ushort(l0) | ((ull)__bfloat16_as_ushort(l1) << 16) |
             ((ull)__bfloat16_as_ushort(l2) << 32) | ((ull)__bfloat16_as_ushort(l3) << 48);
    ((ull*)H)[i] = ph;
    ((ull*)L)[i] = pl;
}

// ================= fused relu+bias: bufA=relu(bufB+b1); bufB=dis^2*bufA =====
__global__ void k_relu_bias(const float* __restrict__ b1, int n) {
    int idx = blockIdx.x * blockDim.x + threadIdx.x;
    int total = n * (MIDD / 4);
    if (idx >= total) return;
    int node = idx >> 6;
    int j = idx & 63;
    float4 b = ((const float4*)b1)[j];
    float4 v = ((const float4*)g_bufB)[idx];
    v.x = fmaxf(v.x + b.x, 0.f);
    v.y = fmaxf(v.y + b.y, 0.f);
    v.z = fmaxf(v.z + b.z, 0.f);
    v.w = fmaxf(v.w + b.w, 0.f);
    ((float4*)g_bufA)[idx] = v;
    float ds = g_dis[node];
    float w = ds * ds;
    v.x *= w; v.y *= w; v.z *= w; v.w *= w;
    ((float4*)g_bufB)[idx] = v;
}

// ================= edge aggregation =================
__global__ void k_edge_agg(const float* __restrict__ feat,
                           float* __restrict__ out, int E) {
    int lane = threadIdx.x & 31;
    int gw = (blockIdx.x * blockDim.x + threadIdx.x) >> 5;
    int nw = (gridDim.x * blockDim.x) >> 5;
    for (int e = gw; e < E; e += nw) {
        int s = __ldg(&g_src[e]);
        int d = __ldg(&g_dst[e]);
        float w = __ldg(&g_norm[e]);
        const float4* f = ((const float4*)feat) + (size_t)s * 64 + lane;
        float* ob = out + (size_t)d * 256 + lane * 4;
        float4 v0 = __ldg(f);
        float4 v1 = __ldg(f + 32);
        atomicAdd(ob + 0,   w * v0.x);
        atomicAdd(ob + 1,   w * v0.y);
        atomicAdd(ob + 2,   w * v0.z);
        atomicAdd(ob + 3,   w * v0.w);
        atomicAdd(ob + 128, w * v1.x);
        atomicAdd(ob + 129, w * v1.y);
        atomicAdd(ob + 130, w * v1.z);
        atomicAdd(ob + 131, w * v1.w);
    }
}

// ================= mma.sync bf16 hi/lo GEMM =================
// C[M,N] = A[M,K](fp32, pre-split into Ah/Al bf16) @ Wt^T, Wt hi/lo is [N,K].
// CTA tile 128x128, BK=32. 8 warps: 4(M) x 2(N); warp tile 32x64.
// 3-term hi/lo: AhBh + AhBl + AlBh. Optional bias; optional C2 = dis^2 * C.
#define ASTR 40   // smem row stride in bf16 (80B; conflict-free for ldmatrix)

__global__ __launch_bounds__(256) void mma_gemm(
    const __nv_bfloat16* __restrict__ Ah, const __nv_bfloat16* __restrict__ Al,
    const __nv_bfloat16* __restrict__ Bh, const __nv_bfloat16* __restrict__ Bl,
    float* __restrict__ C, float* __restrict__ C2, const float* __restrict__ bias,
    int M, int K, int ldc)
{
    __shared__ __nv_bfloat16 sAh[128 * ASTR], sAl[128 * ASTR];
    __shared__ __nv_bfloat16 sBh[128 * ASTR], sBl[128 * ASTR];
    const int tid = threadIdx.x;
    const int lane = tid & 31;
    const int wid = tid >> 5;
    const int wm = wid >> 1;         // 0..3
    const int wn = wid & 1;          // 0..1
    const int rowBase = blockIdx.y * 128;
    const int colBase = blockIdx.x * 128;

    float acc[2][8][4];
#pragma unroll
    for (int i = 0; i < 2; i++)
#pragma unroll
        for (int j = 0; j < 8; j++)
#pragma unroll
            for (int q = 0; q < 4; q++) acc[i][j][q] = 0.f;

    const int lr = tid >> 1;          // 0..127 (tile row / B n-row)
    const int lc = (tid & 1) * 16;    // 0 or 16

    for (int k0 = 0; k0 < K; k0 += 32) {
        // ---- load A tile (128 x 32 bf16, hi+lo) ----
        {
            int gr = rowBase + lr;
            uint4 vh0, vh1, vl0, vl1;
            if (gr < M) {
                const __nv_bfloat16* ph = Ah + (size_t)gr * K + k0 + lc;
                const __nv_bfloat16* pl = Al + (size_t)gr * K + k0 + lc;
                vh0 = *(const uint4*)ph;       vh1 = *(const uint4*)(ph + 8);
                vl0 = *(const uint4*)pl;       vl1 = *(const uint4*)(pl + 8);
            } else {
                vh0 = vh1 = vl0 = vl1 = make_uint4(0, 0, 0, 0);
            }
            *(uint4*)&sAh[lr * ASTR + lc]     = vh0;
            *(uint4*)&sAh[lr * ASTR + lc + 8] = vh1;
            *(uint4*)&sAl[lr * ASTR + lc]     = vl0;
            *(uint4*)&sAl[lr * ASTR + lc + 8] = vl1;
        }
        // ---- load B tile (128 n-rows x 32 k, hi+lo); N always multiple of 128 ----
        {
            const __nv_bfloat16* ph = Bh + (size_t)(colBase + lr) * K + k0 + lc;
            const __nv_bfloat16* pl = Bl + (size_t)(colBase + lr) * K + k0 + lc;
            *(uint4*)&sBh[lr * ASTR + lc]     = *(const uint4*)ph;
            *(uint4*)&sBh[lr * ASTR + lc + 8] = *(const uint4*)(ph + 8);
            *(uint4*)&sBl[lr * ASTR + lc]     = *(const uint4*)pl;
            *(uint4*)&sBl[lr * ASTR + lc + 8] = *(const uint4*)(pl + 8);
        }
        __syncthreads();

#pragma unroll
        for (int s = 0; s < 2; s++) {          // two k16 steps
            uint32_t ah[2][4], al[2][4], bh[8][2], bl[8][2];
#pragma unroll
            for (int i = 0; i < 2; i++) {
                int row = wm * 32 + i * 16 + (lane & 15);
                int col = s * 16 + (lane >> 4) * 8;
                ldsm_x4(ah[i], smem_u32(&sAh[row * ASTR + col]));
                ldsm_x4(al[i], smem_u32(&sAl[row * ASTR + col]));
            }
#pragma unroll
            for (int j = 0; j < 8; j++) {
                int nrow = wn * 64 + j * 8 + (lane & 7);
                int col = s * 16 + ((lane >> 3) & 1) * 8;
                ldsm_x2(bh[j], smem_u32(&sBh[nrow * ASTR + col]));
                ldsm_x2(bl[j], smem_u32(&sBl[nrow * ASTR + col]));
            }
#pragma unroll
            for (int i = 0; i < 2; i++)
#pragma unroll
                for (int j = 0; j < 8; j++) {
                    mma_bf16(acc[i][j], ah[i], bh[j]);
                    mma_bf16(acc[i][j], ah[i], bl[j]);
                    mma_bf16(acc[i][j], al[i], bh[j]);
                }
        }
        __syncthreads();
    }

    // ---- epilogue ----
#pragma unroll
    for (int i = 0; i < 2; i++) {
        int r0 = rowBase + wm * 32 + i * 16 + (lane >> 2);
        int r1 = r0 + 8;
        float s0 = 0.f, s1 = 0.f;
        if (C2) {
            if (r0 < M) { float d = g_dis[r0]; s0 = d * d; }
            if (r1 < M) { float d = g_dis[r1]; s1 = d * d; }
        }
#pragma unroll
        for (int j = 0; j < 8; j++) {
            int col = colBase + wn * 64 + j * 8 + 2 * (lane & 3);
            float b0 = 0.f, b1 = 0.f;
            if (bias) { b0 = bias[col]; b1 = bias[col + 1]; }
            if (r0 < M) {
                float2 o = make_float2(acc[i][j][0] + b0, acc[i][j][1] + b1);
                *(float2*)(C + (size_t)r0 * ldc + col) = o;
                if (C2) *(float2*)(C2 + (size_t)r0 * ldc + col) =
                    make_float2(o.x * s0, o.y * s0);
            }
            if (r1 < M) {
                float2 o = make_float2(acc[i][j][2] + b0, acc[i][j][3] + b1);
                *(float2*)(C + (size_t)r1 * ldc + col) = o;
                if (C2) *(float2*)(C2 + (size_t)r1 * ldc + col) =
                    make_float2(o.x * s1, o.y * s1);
            }
        }
    }
}

extern "C" void kernel_launch(void* const* d_in, const int* in_sizes, int n_in,
                              void* d_out, int out_size) {
    if (n_in < 6) return;
    const float* x  = (const float*)d_in[0];
    const void*  ei = d_in[1];
    const float* W1 = (const float*)d_in[2];
    const float* b1 = (const float*)d_in[3];
    const float* W2 = (const float*)d_in[4];
    const float* b2 = (const float*)d_in[5];

    int n = in_sizes[0] / IND;     // 50000
    int E = in_sizes[1] / 2;       // 1600000

    float *bufA, *bufB;
    __nv_bfloat16 *w1h, *w1l, *w2h, *w2l, *ah, *al;
    cudaGetSymbolAddress((void**)&bufA, g_bufA);
    cudaGetSymbolAddress((void**)&bufB, g_bufB);
    cudaGetSymbolAddress((void**)&w1h, g_w1t_hi);
    cudaGetSymbolAddress((void**)&w1l, g_w1t_lo);
    cudaGetSymbolAddress((void**)&w2h, g_w2t_hi);
    cudaGetSymbolAddress((void**)&w2l, g_w2t_lo);
    cudaGetSymbolAddress((void**)&ah, g_ah);
    cudaGetSymbolAddress((void**)&al, g_al);

    const int T = 256;
    int nb_n  = (n + T - 1) / T;
    int nb_e  = (E + T - 1) / T;
    int nb_f4 = (n * (MIDD / 4) + T - 1) / T;
    int nb_w  = (IND * MIDD + T - 1) / T;
    int mtiles = (n + 127) / 128;

    // edge-index dtype detection + int32 materialization
    k_detect<<<1, 256>>>((const int*)ei, E);
    k_convert<<<nb_e, T>>>(ei, E, n);

    // normalization coefficients
    k_init_deg<<<nb_n, T>>>(n);
    k_deg<<<nb_e, T>>>(E);
    k_dis<<<nb_n, T>>>(n);
    k_norm<<<nb_e, T>>>(E);

    // weight transpose + hi/lo split (small)
    k_wt<<<nb_w, T>>>(W1, w1h, w1l, IND, MIDD);
    k_wt<<<nb_w, T>>>(W2, w2h, w2l, MIDD, IND);

    // layer 1: split X, then bufA = X @ W1 ; bufB = dis^2 * bufA (fused seed)
    int t4a = n * IND / 4;
    k_split<<<(t4a + T - 1) / T, T>>>(x, ah, al, t4a);
    mma_gemm<<<dim3(MIDD / 128, mtiles), 256>>>(ah, al, w1h, w1l,
                                                bufA, bufB, nullptr, n, IND, MIDD);
    // agg1 += edge messages
    k_edge_agg<<<8192, 256>>>(bufA, bufB, E);
    // h = relu(agg1 + b1) -> bufA ; bufB = dis^2 * h (seed for layer 2)
    k_relu_bias<<<nb_f4, T>>>(b1, n);
    // agg2 += edge messages
    k_edge_agg<<<8192, 256>>>(bufA, bufB, E);
    // layer 2: split agg2, then out = agg2 @ W2 + b2
    int t4b = n * MIDD / 4;
    k_split<<<(t4b + T - 1) / T, T>>>(bufB, ah, al, t4b);
    mma_gemm<<<dim3(IND / 128, mtiles), 256>>>(ah, al, w2h, w2l,
                                               (float*)d_out, nullptr, b2, n, MIDD, IND);
}